// round 13
// baseline (speedup 1.0000x reference)
#include <cuda_runtime.h>
#include <cstdint>

// K1 (UNCHANGED from R12, measured 76.6us ~ LTS cap): per-(half,type,graph) CTA
//     streams half a graph's rows -> partial SUM in g_part, __ldcs + 4-deep MLP.
// K2: combine -> transposed duplicated mean aTD[k][g]={m,m}; register-blocked
//     outer product 8(M)x4(N) per thread; B from smem WS staged in 16-k chunks
//     (conflict-free 16B-stride LDS.128), A via broadcast LDS.128, 16 FFMA2/k.
//
// Inputs: 0:x_a 1:W_a 2:b_a 3:x_b 4:W_b 5:b_b 6:ptr_a 7:ptr_b
// Output: [4096, 512] f32 (cols 0..255 type a, 256..511 type b)

#define NGRAPH 4096
#define D_IN   128
#define D_OUT  256
#define TM     32    // graphs per GEMM tile

// layout: plane (h*2 + t), then graph, then col
__device__ float g_part[4 * NGRAPH * D_IN];   // 8 MB scratch

// ---------------- Kernel 1: half-graph partial sums ----------------
__global__ __launch_bounds__(128, 8)
void seg_sum_kernel(const float* __restrict__ x_a, const float* __restrict__ x_b,
                    const int* __restrict__ ptr_a, const int* __restrict__ ptr_b)
{
    const int bid = blockIdx.x;               // 0..16383
    const int h   = bid >> 13;                // half
    const int t   = (bid >> 12) & 1;          // type
    const int g   = bid & (NGRAPH - 1);

    const float* __restrict__ x   = t ? x_b   : x_a;
    const int*   __restrict__ ptr = t ? ptr_b : ptr_a;

    const int tid = threadIdx.x;              // 128 = 4 warps
    const int w   = tid >> 5;
    const int c4  = tid & 31;

    const int r0  = ptr[g];
    const int r1  = ptr[g + 1];
    const int mid = r0 + ((r1 - r0) >> 1);
    const int rs  = h ? mid : r0;
    const int re  = h ? r1  : mid;

    const float4* __restrict__ x4 = reinterpret_cast<const float4*>(x);

    float4 a0 = make_float4(0.f,0.f,0.f,0.f);
    float4 a1 = make_float4(0.f,0.f,0.f,0.f);
    float4 a2 = make_float4(0.f,0.f,0.f,0.f);
    float4 a3 = make_float4(0.f,0.f,0.f,0.f);

    int i = rs + w;                           // 4 rows in flight per warp
    for (; i + 12 < re; i += 16) {
        float4 v0 = __ldcs(&x4[(size_t)i        * 32 + c4]);
        float4 v1 = __ldcs(&x4[(size_t)(i + 4)  * 32 + c4]);
        float4 v2 = __ldcs(&x4[(size_t)(i + 8)  * 32 + c4]);
        float4 v3 = __ldcs(&x4[(size_t)(i + 12) * 32 + c4]);
        a0.x += v0.x; a0.y += v0.y; a0.z += v0.z; a0.w += v0.w;
        a1.x += v1.x; a1.y += v1.y; a1.z += v1.z; a1.w += v1.w;
        a2.x += v2.x; a2.y += v2.y; a2.z += v2.z; a2.w += v2.w;
        a3.x += v3.x; a3.y += v3.y; a3.z += v3.z; a3.w += v3.w;
    }
    for (; i < re; i += 4) {
        float4 v0 = __ldcs(&x4[(size_t)i * 32 + c4]);
        a0.x += v0.x; a0.y += v0.y; a0.z += v0.z; a0.w += v0.w;
    }
    a0.x += a1.x + a2.x + a3.x;
    a0.y += a1.y + a2.y + a3.y;
    a0.z += a1.z + a2.z + a3.z;
    a0.w += a1.w + a2.w + a3.w;

    __shared__ float red[4][D_IN];
    red[w][c4 * 4 + 0] = a0.x;
    red[w][c4 * 4 + 1] = a0.y;
    red[w][c4 * 4 + 2] = a0.z;
    red[w][c4 * 4 + 3] = a0.w;
    __syncthreads();

    float s = red[0][tid] + red[1][tid] + red[2][tid] + red[3][tid];
    g_part[(((size_t)h * 2 + t) * NGRAPH + g) * D_IN + tid] = s;
}

// ---------------- Kernel 2: combine + register-blocked GEMM + bias ----------------
#define APAD 34   // row stride (float2) for aTD: even -> 16B-aligned rows
#define KCH  16   // k per WS chunk

__global__ __launch_bounds__(256, 2)
void gemm_kernel(const float* __restrict__ W_a, const float* __restrict__ b_a,
                 const float* __restrict__ W_b, const float* __restrict__ b_b,
                 const int* __restrict__ ptr_a, const int* __restrict__ ptr_b,
                 float* __restrict__ out)
{
    const int t  = blockIdx.y;
    const int g0 = blockIdx.x * TM;

    const float* __restrict__ W    = t ? W_b   : W_a;
    const float* __restrict__ bias = t ? b_b   : b_a;
    const int*   __restrict__ ptr  = t ? ptr_b : ptr_a;

    __shared__ float2 aTD[D_IN][APAD];     // [k][graph] mean, duplicated {v,v}; ~34.8 KB
    __shared__ float  WS[KCH][D_OUT];      // 16 KB: one 16-k chunk of W
    __shared__ float  invc[TM];

    const int tid  = threadIdx.x;          // 256 = 8 warps
    const int lane = tid & 31;
    const int warp = tid >> 5;
    const int gg   = warp >> 1;            // graph group 0..3 -> graphs [8*gg, 8*gg+8)
    const int ch   = warp & 1;             // column half
    const int colq = ch * 32 + lane;       // float4 column index 0..63 (16B lane stride)

    if (tid < TM) {
        int m = g0 + tid;
        int c = ptr[m + 1] - ptr[m];
        invc[tid] = (c > 0) ? 1.f / (float)c : 0.f;
    }
    __syncthreads();

    // combine halves -> transposed duplicated mean tile.
    // 32 rows x 32 float4 = 1024 float4, 4 per thread (coalesced reads).
    {
        const float4* p0 = reinterpret_cast<const float4*>(g_part) + ((size_t)t * NGRAPH + g0) * 32;
        const float4* p1 = p0 + (size_t)2 * NGRAPH * 32;
        #pragma unroll
        for (int j = 0; j < 4; j++) {
            int i4  = tid + 256 * j;       // row = i4>>5 (graph), k4 = i4&31
            int row = i4 >> 5;
            int k4  = i4 & 31;
            float4 u = p0[row * 32 + k4];
            float4 v = p1[row * 32 + k4];
            float  r = invc[row];
            float m0 = (u.x + v.x) * r;
            float m1 = (u.y + v.y) * r;
            float m2 = (u.z + v.z) * r;
            float m3 = (u.w + v.w) * r;
            aTD[4 * k4 + 0][row] = make_float2(m0, m0);
            aTD[4 * k4 + 1][row] = make_float2(m1, m1);
            aTD[4 * k4 + 2][row] = make_float2(m2, m2);
            aTD[4 * k4 + 3][row] = make_float2(m3, m3);
        }
    }

    unsigned long long acc[8][2];          // [graph][col-pair]
    #pragma unroll
    for (int i = 0; i < 8; i++) { acc[i][0] = 0ull; acc[i][1] = 0ull; }

    const float4* __restrict__ W4 = reinterpret_cast<const float4*>(W);

    #pragma unroll 1
    for (int kc = 0; kc < D_IN / KCH; kc++) {
        __syncthreads();                   // protect WS (covers aTD fill on kc=0)
        {
            // stage 16 k x 256 cols = 1024 float4, 4 per thread, coalesced
            float4* ws4 = reinterpret_cast<float4*>(&WS[0][0]);
            #pragma unroll
            for (int j = 0; j < 4; j++)
                ws4[tid + 256 * j] = __ldg(&W4[kc * (KCH * 64) + tid + 256 * j]);
        }
        __syncthreads();

        #pragma unroll
        for (int k = 0; k < KCH; k++) {
            // B frag: 4 cols via LDS.128, 16B lane stride -> conflict-free
            ulonglong2 b = *reinterpret_cast<const ulonglong2*>(&WS[k][4 * colq]);
            // A frag: 8 duplicated graphs, warp-uniform -> broadcast LDS.128 x4
            const float2* ap = &aTD[kc * KCH + k][8 * gg];
            ulonglong2 a01 = *reinterpret_cast<const ulonglong2*>(ap + 0);
            ulonglong2 a23 = *reinterpret_cast<const ulonglong2*>(ap + 2);
            ulonglong2 a45 = *reinterpret_cast<const ulonglong2*>(ap + 4);
            ulonglong2 a67 = *reinterpret_cast<const ulonglong2*>(ap + 6);

            asm("fma.rn.f32x2 %0, %1, %2, %0;" : "+l"(acc[0][0]) : "l"(a01.x), "l"(b.x));
            asm("fma.rn.f32x2 %0, %1, %2, %0;" : "+l"(acc[0][1]) : "l"(a01.x), "l"(b.y));
            asm("fma.rn.f32x2 %0, %1, %2, %0;" : "+l"(acc[1][0]) : "l"(a01.y), "l"(b.x));
            asm("fma.rn.f32x2 %0, %1, %2, %0;" : "+l"(acc[1][1]) : "l"(a01.y), "l"(b.y));
            asm("fma.rn.f32x2 %0, %1, %2, %0;" : "+l"(acc[2][0]) : "l"(a23.x), "l"(b.x));
            asm("fma.rn.f32x2 %0, %1, %2, %0;" : "+l"(acc[2][1]) : "l"(a23.x), "l"(b.y));
            asm("fma.rn.f32x2 %0, %1, %2, %0;" : "+l"(acc[3][0]) : "l"(a23.y), "l"(b.x));
            asm("fma.rn.f32x2 %0, %1, %2, %0;" : "+l"(acc[3][1]) : "l"(a23.y), "l"(b.y));
            asm("fma.rn.f32x2 %0, %1, %2, %0;" : "+l"(acc[4][0]) : "l"(a45.x), "l"(b.x));
            asm("fma.rn.f32x2 %0, %1, %2, %0;" : "+l"(acc[4][1]) : "l"(a45.x), "l"(b.y));
            asm("fma.rn.f32x2 %0, %1, %2, %0;" : "+l"(acc[5][0]) : "l"(a45.y), "l"(b.x));
            asm("fma.rn.f32x2 %0, %1, %2, %0;" : "+l"(acc[5][1]) : "l"(a45.y), "l"(b.y));
            asm("fma.rn.f32x2 %0, %1, %2, %0;" : "+l"(acc[6][0]) : "l"(a67.x), "l"(b.x));
            asm("fma.rn.f32x2 %0, %1, %2, %0;" : "+l"(acc[6][1]) : "l"(a67.x), "l"(b.y));
            asm("fma.rn.f32x2 %0, %1, %2, %0;" : "+l"(acc[7][0]) : "l"(a67.y), "l"(b.x));
            asm("fma.rn.f32x2 %0, %1, %2, %0;" : "+l"(acc[7][1]) : "l"(a67.y), "l"(b.y));
        }
    }

    // epilogue: bias + empty-graph mask
    const float4 bv = __ldg(reinterpret_cast<const float4*>(bias) + colq);
    float4* out4 = reinterpret_cast<float4*>(out);

    #pragma unroll
    for (int i = 0; i < 8; i++) {
        const int ml = 8 * gg + i;
        const int m  = g0 + ml;
        float4 o;
        asm("mov.b64 {%0, %1}, %2;" : "=f"(o.x), "=f"(o.y) : "l"(acc[i][0]));
        asm("mov.b64 {%0, %1}, %2;" : "=f"(o.z), "=f"(o.w) : "l"(acc[i][1]));
        if (invc[ml] > 0.f) {
            o.x += bv.x; o.y += bv.y; o.z += bv.z; o.w += bv.w;
        } else {
            o = make_float4(0.f, 0.f, 0.f, 0.f);
        }
        out4[(size_t)m * 128 + t * 64 + colq] = o;
    }
}

extern "C" void kernel_launch(void* const* d_in, const int* in_sizes, int n_in,
                              void* d_out, int out_size)
{
    const float* x_a   = (const float*)d_in[0];
    const float* W_a   = (const float*)d_in[1];
    const float* b_a   = (const float*)d_in[2];
    const float* x_b   = (const float*)d_in[3];
    const float* W_b   = (const float*)d_in[4];
    const float* b_b   = (const float*)d_in[5];
    const int*   ptr_a = (const int*)d_in[6];
    const int*   ptr_b = (const int*)d_in[7];
    float* out = (float*)d_out;

    seg_sum_kernel<<<4 * NGRAPH, 128>>>(x_a, x_b, ptr_a, ptr_b);

    dim3 gridB(NGRAPH / TM, 2);
    gemm_kernel<<<gridB, 256>>>(W_a, b_a, W_b, b_b, ptr_a, ptr_b, out);
}